// round 4
// baseline (speedup 1.0000x reference)
#include <cuda_runtime.h>

// PLIF spiking neuron forward — round 4: single-wave persistent grid.
// x: [B=16, T=32, C=128, H=32, W=32] fp32; a scalar; out spikes fp32 {0,1}.
//
// Steady-state HBM rate is pinned at ~6.0 TB/s for this 1:1 R/W mix across
// three prior kernel shapes -> remaining lever is wave/tail geometry.
// Launch exactly one wave (148 SMs x 6 resident blocks) and grid-stride over
// float4 sites, so every SM carries an identical load and there are no
// wave transitions or partial-wave tails.

constexpr int B = 16;
constexpr int T = 32;
constexpr int C = 128;
constexpr int H = 32;
constexpr int W = 32;
constexpr int CHW_V4   = (C * H * W) / 4;   // 32768 float4 per (b,t) slice
constexpr int TOTAL_V4 = B * CHW_V4;        // 524288 float4 sites
constexpr int UNROLL   = 8;

constexpr int NUM_SMS       = 148;
constexpr int BLOCKS_PER_SM = 6;            // 42-44 regs @ 256 thr -> 6 resident
constexpr int GRID          = NUM_SMS * BLOCKS_PER_SM;  // 888
constexpr int THREADS       = 256;

__global__ __launch_bounds__(THREADS, BLOCKS_PER_SM)
void plif_fwd_kernel(const float4* __restrict__ x,
                     const float*  __restrict__ a,
                     float4*       __restrict__ out)
{
    float av = __ldg(a);
    float decay = 1.0f / (1.0f + expf(-av));

    const int stride = GRID * THREADS;

    for (int i = blockIdx.x * THREADS + threadIdx.x; i < TOTAL_V4; i += stride) {
        // CHW_V4 is a power of two -> shifts, not divides.
        int b    = i >> 15;            // i / CHW_V4
        int chw  = i & (CHW_V4 - 1);
        int base = b * (T * CHW_V4) + chw;

        float mx = 0.0f, my = 0.0f, mz = 0.0f, mw = 0.0f;

        #pragma unroll
        for (int tb = 0; tb < T; tb += UNROLL) {
            float4 xi[UNROLL];
            float4 s[UNROLL];

            // Read burst: 8 independent LDG.128 in flight.
            #pragma unroll
            for (int u = 0; u < UNROLL; u++)
                xi[u] = __ldcs(&x[base + (tb + u) * CHW_V4]);

            // Serial recurrence (registers only).
            #pragma unroll
            for (int u = 0; u < UNROLL; u++) {
                mx = fmaf(decay, mx, xi[u].x);
                my = fmaf(decay, my, xi[u].y);
                mz = fmaf(decay, mz, xi[u].z);
                mw = fmaf(decay, mw, xi[u].w);

                s[u].x = (mx >= 1.0f) ? 1.0f : 0.0f;
                s[u].y = (my >= 1.0f) ? 1.0f : 0.0f;
                s[u].z = (mz >= 1.0f) ? 1.0f : 0.0f;
                s[u].w = (mw >= 1.0f) ? 1.0f : 0.0f;

                mx = (mx >= 1.0f) ? 0.0f : mx;
                my = (my >= 1.0f) ? 0.0f : my;
                mz = (mz >= 1.0f) ? 0.0f : mz;
                mw = (mw >= 1.0f) ? 0.0f : mw;
            }

            // Write burst: 8 back-to-back STG.128.
            #pragma unroll
            for (int u = 0; u < UNROLL; u++)
                __stcs(&out[base + (tb + u) * CHW_V4], s[u]);
        }
    }
}

extern "C" void kernel_launch(void* const* d_in, const int* in_sizes, int n_in,
                              void* d_out, int out_size)
{
    const float4* x   = (const float4*)d_in[0];
    const float*  a   = (const float*)d_in[1];
    float4*       out = (float4*)d_out;

    plif_fwd_kernel<<<GRID, THREADS>>>(x, a, out);
}

// round 5
// speedup vs baseline: 1.1856x; 1.1856x over previous
#include <cuda_runtime.h>

// PLIF spiking neuron forward — round 5: 256-bit (v8.f32) global accesses.
// x: [B=16, T=32, C=128, H=32, W=32] fp32; a scalar; out spikes fp32 {0,1}.
//
// Geometry reverted to the flat one-chunk-per-thread launch (rounds 1-3 all
// ~88us / 73% DRAM; round-4 persistent grid regressed). New lever: sm_100a
// 256-bit LDG/STG (ld/st.global.v8.f32) halves LSU/L1tex wavefronts per byte
// and doubles request granularity at the memory controller.

constexpr int B = 16;
constexpr int T = 32;
constexpr int C = 128;
constexpr int H = 32;
constexpr int W = 32;
constexpr int CHW      = C * H * W;          // 131072 floats per (b,t) slice
constexpr int CHW_V8   = CHW / 8;            // 16384 v8 chunks per slice
constexpr int TOTAL_V8 = B * CHW_V8;         // 262144 v8 sites
constexpr int UNROLL   = 4;

__device__ __forceinline__ void ldg256_cs(const float* p, float* v)
{
    asm volatile(
        "ld.global.cs.v8.f32 {%0,%1,%2,%3,%4,%5,%6,%7}, [%8];"
        : "=f"(v[0]), "=f"(v[1]), "=f"(v[2]), "=f"(v[3]),
          "=f"(v[4]), "=f"(v[5]), "=f"(v[6]), "=f"(v[7])
        : "l"(p));
}

__device__ __forceinline__ void stg256_cs(float* p, const float* v)
{
    asm volatile(
        "st.global.cs.v8.f32 [%0], {%1,%2,%3,%4,%5,%6,%7,%8};"
        :: "l"(p),
           "f"(v[0]), "f"(v[1]), "f"(v[2]), "f"(v[3]),
           "f"(v[4]), "f"(v[5]), "f"(v[6]), "f"(v[7])
        : "memory");
}

__global__ __launch_bounds__(256)
void plif_fwd_kernel(const float* __restrict__ x,
                     const float* __restrict__ a,
                     float*       __restrict__ out)
{
    int i = blockIdx.x * blockDim.x + threadIdx.x;
    if (i >= TOTAL_V8) return;

    int b    = i >> 14;                // i / CHW_V8
    int chw8 = i & (CHW_V8 - 1);
    long long base = (long long)b * (T * CHW) + (long long)chw8 * 8;

    float av = __ldg(a);
    float decay = 1.0f / (1.0f + expf(-av));

    float mem[8];
    #pragma unroll
    for (int e = 0; e < 8; e++) mem[e] = 0.0f;

    #pragma unroll
    for (int tb = 0; tb < T; tb += UNROLL) {
        float xi[UNROLL][8];

        // Front-batched 256-bit loads: 4 independent LDG.E.256 in flight.
        #pragma unroll
        for (int u = 0; u < UNROLL; u++)
            ldg256_cs(x + base + (long long)(tb + u) * CHW, xi[u]);

        // Recurrence + spike + hard reset, then 256-bit store per step.
        #pragma unroll
        for (int u = 0; u < UNROLL; u++) {
            float s[8];
            #pragma unroll
            for (int e = 0; e < 8; e++) {
                mem[e] = fmaf(decay, mem[e], xi[u][e]);
                bool fire = (mem[e] >= 1.0f);
                s[e]   = fire ? 1.0f : 0.0f;
                mem[e] = fire ? 0.0f : mem[e];
            }
            stg256_cs(out + base + (long long)(tb + u) * CHW, s);
        }
    }
}

extern "C" void kernel_launch(void* const* d_in, const int* in_sizes, int n_in,
                              void* d_out, int out_size)
{
    const float* x   = (const float*)d_in[0];
    const float* a   = (const float*)d_in[1];
    float*       out = (float*)d_out;

    constexpr int THREADS = 256;
    constexpr int BLOCKS  = (TOTAL_V8 + THREADS - 1) / THREADS;  // 1024

    plif_fwd_kernel<<<BLOCKS, THREADS>>>(x, a, out);
}

// round 6
// speedup vs baseline: 1.2093x; 1.0200x over previous
#include <cuda_runtime.h>

// PLIF spiking neuron forward — round 6: v8 (256-bit) accesses + 8-deep
// front-batched read bursts.
// x: [B=16, T=32, C=128, H=32, W=32] fp32; a scalar; out spikes fp32 {0,1}.
//
// Evidence so far: DRAM efficiency (not SM-side parallelism) is the binding
// constraint; the only lever that moved it was wider per-request granularity
// (128b->256b: 73.0% -> 74.6% of spec). This round doubles the read burst
// run-length: 8 back-to-back LDG.E.256 per thread (8KB/warp) before any
// dependent FMA. Occupancy cost is irrelevant (proven insensitive 43%-84%).

constexpr int B = 16;
constexpr int T = 32;
constexpr int C = 128;
constexpr int H = 32;
constexpr int W = 32;
constexpr int CHW      = C * H * W;          // 131072 floats per (b,t) slice
constexpr int CHW_V8   = CHW / 8;            // 16384 v8 chunks per slice
constexpr int TOTAL_V8 = B * CHW_V8;         // 262144 v8 sites
constexpr int UNROLL   = 8;

__device__ __forceinline__ void ldg256_cs(const float* p, float* v)
{
    asm volatile(
        "ld.global.cs.v8.f32 {%0,%1,%2,%3,%4,%5,%6,%7}, [%8];"
        : "=f"(v[0]), "=f"(v[1]), "=f"(v[2]), "=f"(v[3]),
          "=f"(v[4]), "=f"(v[5]), "=f"(v[6]), "=f"(v[7])
        : "l"(p));
}

__device__ __forceinline__ void stg256_cs(float* p, const float* v)
{
    asm volatile(
        "st.global.cs.v8.f32 [%0], {%1,%2,%3,%4,%5,%6,%7,%8};"
        :: "l"(p),
           "f"(v[0]), "f"(v[1]), "f"(v[2]), "f"(v[3]),
           "f"(v[4]), "f"(v[5]), "f"(v[6]), "f"(v[7])
        : "memory");
}

__global__ __launch_bounds__(256)
void plif_fwd_kernel(const float* __restrict__ x,
                     const float* __restrict__ a,
                     float*       __restrict__ out)
{
    int i = blockIdx.x * blockDim.x + threadIdx.x;
    if (i >= TOTAL_V8) return;

    int b    = i >> 14;                // i / CHW_V8
    int chw8 = i & (CHW_V8 - 1);
    long long base = (long long)b * (T * CHW) + (long long)chw8 * 8;

    float av = __ldg(a);
    float decay = 1.0f / (1.0f + expf(-av));

    float mem[8];
    #pragma unroll
    for (int e = 0; e < 8; e++) mem[e] = 0.0f;

    #pragma unroll
    for (int tb = 0; tb < T; tb += UNROLL) {
        float xi[UNROLL][8];

        // 8-deep read burst: 8 independent LDG.E.256 (8KB/warp) in flight.
        #pragma unroll
        for (int u = 0; u < UNROLL; u++)
            ldg256_cs(x + base + (long long)(tb + u) * CHW, xi[u]);

        // Recurrence + spike + hard reset; store each step's result (v8).
        #pragma unroll
        for (int u = 0; u < UNROLL; u++) {
            float s[8];
            #pragma unroll
            for (int e = 0; e < 8; e++) {
                mem[e] = fmaf(decay, mem[e], xi[u][e]);
                bool fire = (mem[e] >= 1.0f);
                s[e]   = fire ? 1.0f : 0.0f;
                mem[e] = fire ? 0.0f : mem[e];
            }
            stg256_cs(out + base + (long long)(tb + u) * CHW, s);
        }
    }
}

extern "C" void kernel_launch(void* const* d_in, const int* in_sizes, int n_in,
                              void* d_out, int out_size)
{
    const float* x   = (const float*)d_in[0];
    const float* a   = (const float*)d_in[1];
    float*       out = (float*)d_out;

    constexpr int THREADS = 256;
    constexpr int BLOCKS  = (TOTAL_V8 + THREADS - 1) / THREADS;  // 1024

    plif_fwd_kernel<<<BLOCKS, THREADS>>>(x, a, out);
}

// round 7
// speedup vs baseline: 1.2143x; 1.0041x over previous
#include <cuda_runtime.h>

// PLIF spiking neuron forward — round 7: 16-deep v8 read/write bursts.
// x: [B=16, T=32, C=128, H=32, W=32] fp32; a scalar; out spikes fp32 {0,1}.
//
// Dose-response established: MC read-burst run length is the only live lever
// (2KB->73.0%, 4KB->74.6%, 8KB->76.4% of spec HBM). This round: 16 back-to-
// back LDG.E.256 per thread (16KB/warp), compute all 16 t-steps, then a
// 16-deep STG.E.256 burst (spikes overwrite the input registers). 128-thread
// blocks give ptxas the full register budget (~160 regs, no spill target).

constexpr int B = 16;
constexpr int T = 32;
constexpr int C = 128;
constexpr int H = 32;
constexpr int W = 32;
constexpr int CHW      = C * H * W;          // 131072 floats per (b,t) slice
constexpr int CHW_V8   = CHW / 8;            // 16384 v8 chunks per slice
constexpr int TOTAL_V8 = B * CHW_V8;         // 262144 v8 sites
constexpr int UNROLL   = 16;

__device__ __forceinline__ void ldg256_cs(const float* p, float* v)
{
    asm volatile(
        "ld.global.cs.v8.f32 {%0,%1,%2,%3,%4,%5,%6,%7}, [%8];"
        : "=f"(v[0]), "=f"(v[1]), "=f"(v[2]), "=f"(v[3]),
          "=f"(v[4]), "=f"(v[5]), "=f"(v[6]), "=f"(v[7])
        : "l"(p));
}

__device__ __forceinline__ void stg256_cs(float* p, const float* v)
{
    asm volatile(
        "st.global.cs.v8.f32 [%0], {%1,%2,%3,%4,%5,%6,%7,%8};"
        :: "l"(p),
           "f"(v[0]), "f"(v[1]), "f"(v[2]), "f"(v[3]),
           "f"(v[4]), "f"(v[5]), "f"(v[6]), "f"(v[7])
        : "memory");
}

__global__ __launch_bounds__(128)
void plif_fwd_kernel(const float* __restrict__ x,
                     const float* __restrict__ a,
                     float*       __restrict__ out)
{
    int i = blockIdx.x * blockDim.x + threadIdx.x;
    if (i >= TOTAL_V8) return;

    int b    = i >> 14;                // i / CHW_V8
    int chw8 = i & (CHW_V8 - 1);
    long long base = (long long)b * (T * CHW) + (long long)chw8 * 8;

    float av = __ldg(a);
    float decay = 1.0f / (1.0f + expf(-av));

    float mem[8];
    #pragma unroll
    for (int e = 0; e < 8; e++) mem[e] = 0.0f;

    #pragma unroll
    for (int tb = 0; tb < T; tb += UNROLL) {
        float xi[UNROLL][8];

        // 16-deep read burst: 16 independent LDG.E.256 (16KB/warp) in flight.
        #pragma unroll
        for (int u = 0; u < UNROLL; u++)
            ldg256_cs(x + base + (long long)(tb + u) * CHW, xi[u]);

        // Recurrence + spike + hard reset; spikes overwrite xi in place.
        #pragma unroll
        for (int u = 0; u < UNROLL; u++) {
            #pragma unroll
            for (int e = 0; e < 8; e++) {
                mem[e] = fmaf(decay, mem[e], xi[u][e]);
                bool fire = (mem[e] >= 1.0f);
                xi[u][e] = fire ? 1.0f : 0.0f;
                mem[e]   = fire ? 0.0f : mem[e];
            }
        }

        // 16-deep write burst: 16 back-to-back STG.E.256.
        #pragma unroll
        for (int u = 0; u < UNROLL; u++)
            stg256_cs(out + base + (long long)(tb + u) * CHW, xi[u]);
    }
}

extern "C" void kernel_launch(void* const* d_in, const int* in_sizes, int n_in,
                              void* d_out, int out_size)
{
    const float* x   = (const float*)d_in[0];
    const float* a   = (const float*)d_in[1];
    float*       out = (float*)d_out;

    constexpr int THREADS = 128;
    constexpr int BLOCKS  = (TOTAL_V8 + THREADS - 1) / THREADS;  // 2048

    plif_fwd_kernel<<<BLOCKS, THREADS>>>(x, a, out);
}